// round 7
// baseline (speedup 1.0000x reference)
#include <cuda_runtime.h>
#include <cstdint>
#include <math.h>

#define NTOK 2048
#define DIM  2048
#define HID  1024
#define NE   8

// ---------------- device scratch ----------------
__device__ int   g_cnt[NE];
__device__ int   g_tok[NE*NTOK];
__device__ float g_scr[NE*NTOK];
__device__ int2  g_map[NTOK];
__device__ float g_h[(size_t)(NE+1)*NTOK*HID];   // per-slot SwiGLU hidden (tf32-rounded)
__device__ float g_o[(size_t)(NE+1)*NTOK*DIM];   // per-slot FFN2 output
// tf32-rounded operand copies
__device__ float g_xc [(size_t)NTOK*DIM];
__device__ float g_w1c[(size_t)NE*HID*DIM];
__device__ float g_w3c[(size_t)NE*HID*DIM];
__device__ float g_w2c[(size_t)NE*DIM*HID];
__device__ float g_sw1c[(size_t)HID*DIM];
__device__ float g_sw2c[(size_t)DIM*HID];
__device__ float g_sw3c[(size_t)HID*DIM];

// ---------------- PTX helpers ----------------
__device__ __forceinline__ uint32_t smem_u32(const void* p) {
    uint32_t a;
    asm("{ .reg .u64 t; cvta.to.shared.u64 t, %1; cvt.u32.u64 %0, t; }" : "=r"(a) : "l"(p));
    return a;
}
__device__ __forceinline__ void cpa16(uint32_t dst, const void* src) {
    asm volatile("cp.async.cg.shared.global [%0], [%1], 16;"
                 :: "r"(dst), "l"(__cvta_generic_to_global(src)) : "memory");
}
__device__ __forceinline__ void cpa_commit() { asm volatile("cp.async.commit_group;" ::: "memory"); }
template<int N> __device__ __forceinline__ void cpa_wait() {
    asm volatile("cp.async.wait_group %0;" :: "n"(N) : "memory");
}
__device__ __forceinline__ void ldsm4(uint32_t* r, uint32_t addr) {
    asm volatile("ldmatrix.sync.aligned.m8n8.x4.shared.b16 {%0,%1,%2,%3}, [%4];"
                 : "=r"(r[0]), "=r"(r[1]), "=r"(r[2]), "=r"(r[3]) : "r"(addr));
}
__device__ __forceinline__ float f2tf_f(float x) {
    float y;
    asm("cvt.rna.tf32.f32 %0, %1;" : "=f"(y) : "f"(x));
    return y;
}
__device__ __forceinline__ void mma8(float* d, const uint32_t* a, const uint32_t* b) {
    asm volatile("mma.sync.aligned.m16n8k8.row.col.f32.tf32.tf32.f32 "
        "{%0,%1,%2,%3}, {%4,%5,%6,%7}, {%8,%9}, {%0,%1,%2,%3};"
        : "+f"(d[0]), "+f"(d[1]), "+f"(d[2]), "+f"(d[3])
        : "r"(a[0]), "r"(a[1]), "r"(a[2]), "r"(a[3]), "r"(b[0]), "r"(b[1]));
}

// ---------------- tf32 pre-round pass ----------------
__global__ void __launch_bounds__(256)
cvt_kernel(const float4* __restrict__ src, float4* __restrict__ dst, int n4) {
    int i = blockIdx.x * blockDim.x + threadIdx.x;
    if (i < n4) {
        float4 v = src[i];
        v.x = f2tf_f(v.x); v.y = f2tf_f(v.y);
        v.z = f2tf_f(v.z); v.w = f2tf_f(v.w);
        dst[i] = v;
    }
}

// ---------------- small kernels ----------------
__global__ void reset_kernel() {
    if (threadIdx.x < NE) g_cnt[threadIdx.x] = 0;
}

__global__ void gate_kernel(const float* __restrict__ x,
                            const float* __restrict__ gw,
                            const float* __restrict__ bias) {
    __shared__ float xs[DIM];
    __shared__ float sc[NE];
    int n = blockIdx.x;
    const float* xr = x + (size_t)n * DIM;
    for (int i = threadIdx.x * 4; i < DIM; i += blockDim.x * 4)
        *(float4*)&xs[i] = *(const float4*)&xr[i];
    __syncthreads();

    int w = threadIdx.x >> 5, lane = threadIdx.x & 31;
    if (w < NE) {
        const float* g = gw + (size_t)w * DIM;
        float s = 0.f;
        for (int j = lane * 4; j < DIM; j += 128) {
            float4 xv = *(float4*)&xs[j];
            float4 gv = *(const float4*)&g[j];
            s += xv.x * gv.x + xv.y * gv.y + xv.z * gv.z + xv.w * gv.w;
        }
        #pragma unroll
        for (int o = 16; o > 0; o >>= 1) s += __shfl_xor_sync(0xffffffffu, s, o);
        if (lane == 0) sc[w] = 1.f / (1.f + expf(-s));
    }
    __syncthreads();

    if (threadIdx.x == 0) {
        int b1 = 0; float v1 = sc[0] + bias[0];
        #pragma unroll
        for (int e = 1; e < NE; e++) {
            float v = sc[e] + bias[e];
            if (v > v1) { v1 = v; b1 = e; }
        }
        int b2 = -1; float v2 = -1e30f;
        #pragma unroll
        for (int e = 0; e < NE; e++) {
            if (e == b1) continue;
            float v = sc[e] + bias[e];
            if (v > v2) { v2 = v; b2 = e; }
        }
        int p1 = atomicAdd(&g_cnt[b1], 1);
        g_tok[b1 * NTOK + p1] = n;
        g_scr[b1 * NTOK + p1] = sc[b1];
        int p2 = atomicAdd(&g_cnt[b2], 1);
        g_tok[b2 * NTOK + p2] = n;
        g_scr[b2 * NTOK + p2] = sc[b2];
        g_map[n] = make_int2(b1 * NTOK + p1, b2 * NTOK + p2);
    }
}

// ================= FFN1: dual tf32 mma GEMM + SwiGLU =================
// 256 thr (8 warps, 2 CTAs/SM), tile 128M x 64N dual, warp 32x32 dual, KB=32 dbuf.
// Operands are pre-rounded to tf32 — no cvt in mainloop.
#define F1_KB     32
#define F1_STG_A  16384
#define F1_STG_B  8192
#define F1_STRIDE (F1_STG_A + 2*F1_STG_B)   // 32768
#define F1_SMEM   (2*F1_STRIDE)             // 65536
#define F1_S      (DIM/F1_KB)               // 64

__global__ void __launch_bounds__(256, 2)
ffn1_mma(const float* __restrict__ xc,
         const float* __restrict__ w1, const float* __restrict__ w3,
         const float* __restrict__ sw1, const float* __restrict__ sw3)
{
    extern __shared__ char smem[];
    __shared__ int toks[128];
    const int e   = blockIdx.z;
    const int cnt = (e < NE) ? g_cnt[e] : NTOK;
    const int m0  = blockIdx.x * 128;
    if (m0 >= cnt) return;
    const int n0  = blockIdx.y * 64;
    const float* W1 = (e < NE) ? w1 + (size_t)e * HID * DIM : sw1;
    const float* W3 = (e < NE) ? w3 + (size_t)e * HID * DIM : sw3;

    const int tid = threadIdx.x;
    if (tid < 128) {
        int r = m0 + tid;
        toks[tid] = (e < NE) ? g_tok[e * NTOK + (r < cnt ? r : cnt - 1)] : r;
    }
    __syncthreads();
    const uint32_t sb = smem_u32(smem);

    const float* aSrc[4]; uint32_t aDst[4];
    #pragma unroll
    for (int i = 0; i < 4; i++) {
        int g = tid + i * 256, row = g >> 3, seg = g & 7;
        aSrc[i] = xc + (size_t)toks[row] * DIM + seg * 4;
        aDst[i] = sb + row * 128 + ((seg * 16) ^ ((row & 7) << 4));
    }
    const float *b1Src[2], *b3Src[2]; uint32_t bDst[2];
    #pragma unroll
    for (int i = 0; i < 2; i++) {
        int g = tid + i * 256, row = g >> 3, seg = g & 7;   // row 0..63
        b1Src[i] = W1 + (size_t)(n0 + row) * DIM + seg * 4;
        b3Src[i] = W3 + (size_t)(n0 + row) * DIM + seg * 4;
        bDst[i]  = sb + F1_STG_A + row * 128 + ((seg * 16) ^ ((row & 7) << 4));
    }

    auto load_stage = [&](int s) {
        uint32_t so = (uint32_t)(s & 1) * F1_STRIDE;
        int k0 = s * F1_KB;
        #pragma unroll
        for (int i = 0; i < 4; i++) cpa16(aDst[i] + so, aSrc[i] + k0);
        #pragma unroll
        for (int i = 0; i < 2; i++) cpa16(bDst[i] + so, b1Src[i] + k0);
        #pragma unroll
        for (int i = 0; i < 2; i++) cpa16(bDst[i] + so + F1_STG_B, b3Src[i] + k0);
        cpa_commit();
    };

    const int lane = tid & 31, w = tid >> 5;
    const int wm = w & 3, wn = w >> 2;
    const int matid = lane >> 3, mrow = lane & 7;
    const uint32_t swz = (uint32_t)(mrow << 4);

    uint32_t aRB[2];
    #pragma unroll
    for (int mc = 0; mc < 2; mc++) {
        int row = wm * 32 + mc * 16 + (matid & 1) * 8 + mrow;
        aRB[mc] = sb + row * 128;
    }
    const uint32_t aKS = (uint32_t)((matid >> 1) * 16);

    uint32_t bRB[2];
    #pragma unroll
    for (int nb = 0; nb < 2; nb++) {
        int n = wn * 32 + nb * 16 + (matid >> 1) * 8 + mrow;
        bRB[nb] = sb + F1_STG_A + n * 128;
    }
    const uint32_t bKS = (uint32_t)((matid & 1) * 16);

    float accG[2][4][4] = {};
    float accU[2][4][4] = {};

    load_stage(0);
    load_stage(1);
    for (int s = 0; s < F1_S; s++) {
        if (s == F1_S - 1) cpa_wait<0>(); else cpa_wait<1>();
        __syncthreads();
        const uint32_t so = (uint32_t)(s & 1) * F1_STRIDE;
        #pragma unroll
        for (int ks = 0; ks < 4; ks++) {
            uint32_t aoff = so + ((ks * 32 + aKS) ^ swz);
            uint32_t boff = so + ((ks * 32 + bKS) ^ swz);
            uint32_t aF[2][4], bF1[2][4], bF3[2][4];
            ldsm4(aF[0], aRB[0] + aoff);
            ldsm4(aF[1], aRB[1] + aoff);
            #pragma unroll
            for (int nb = 0; nb < 2; nb++) {
                ldsm4(bF1[nb], bRB[nb] + boff);
                ldsm4(bF3[nb], bRB[nb] + boff + F1_STG_B);
            }
            #pragma unroll
            for (int mc = 0; mc < 2; mc++)
                #pragma unroll
                for (int nb = 0; nb < 2; nb++) {
                    mma8(accG[mc][nb*2],   aF[mc], &bF1[nb][0]);
                    mma8(accG[mc][nb*2+1], aF[mc], &bF1[nb][2]);
                    mma8(accU[mc][nb*2],   aF[mc], &bF3[nb][0]);
                    mma8(accU[mc][nb*2+1], aF[mc], &bF3[nb][2]);
                }
        }
        __syncthreads();
        if (s + 2 < F1_S) load_stage(s + 2);
    }

    // epilogue: h = tf32_round( silu(sc*g) * (sc*u) )  -> ffn2 needs no cvt
    #pragma unroll
    for (int mc = 0; mc < 2; mc++)
        #pragma unroll
        for (int h = 0; h < 2; h++) {
            int r = m0 + wm * 32 + mc * 16 + (lane >> 2) + h * 8;
            if (r < cnt) {
                float scv = (e < NE) ? g_scr[e * NTOK + r] : 1.f;
                float* hrow = g_h + ((size_t)e * NTOK + r) * HID + n0 + wn * 32 + (lane & 3) * 2;
                #pragma unroll
                for (int nc = 0; nc < 4; nc++) {
                    float g0 = accG[mc][nc][h*2+0] * scv, u0 = accU[mc][nc][h*2+0] * scv;
                    float g1 = accG[mc][nc][h*2+1] * scv, u1 = accU[mc][nc][h*2+1] * scv;
                    float2 v;
                    v.x = f2tf_f(g0 * (1.f / (1.f + __expf(-g0))) * u0);
                    v.y = f2tf_f(g1 * (1.f / (1.f + __expf(-g1))) * u1);
                    *(float2*)(hrow + nc * 8) = v;
                }
            }
        }
}

// ================= FFN2: tf32 mma GEMM =================
// 256 thr (8 warps, 2 CTAs/SM), tile 128M x 128N, warp 32x64, KB=32 dbuf. No in-loop cvt.
#define F2_KB     32
#define F2_STG_A  16384
#define F2_STG_B  16384
#define F2_STRIDE (F2_STG_A + F2_STG_B)     // 32768
#define F2_SMEM   (2*F2_STRIDE)             // 65536
#define F2_S      (HID/F2_KB)               // 32

__global__ void __launch_bounds__(256, 2)
ffn2_mma(const float* __restrict__ w2, const float* __restrict__ sw2)
{
    extern __shared__ char smem[];
    const int e   = blockIdx.z;
    const int cnt = (e < NE) ? g_cnt[e] : NTOK;
    const int m0  = blockIdx.x * 128;
    if (m0 >= cnt) return;
    const int n0  = blockIdx.y * 128;
    const float* W2 = (e < NE) ? w2 + (size_t)e * DIM * HID : sw2;
    const float* A  = g_h + ((size_t)e * NTOK + m0) * HID;

    const int tid = threadIdx.x;
    const uint32_t sb = smem_u32(smem);

    const float *aSrc[4], *bSrc[4]; uint32_t gDst[4];
    #pragma unroll
    for (int i = 0; i < 4; i++) {
        int g = tid + i * 256, row = g >> 3, seg = g & 7;
        aSrc[i] = A  + (size_t)row * HID + seg * 4;
        bSrc[i] = W2 + (size_t)(n0 + row) * HID + seg * 4;
        gDst[i] = sb + row * 128 + ((seg * 16) ^ ((row & 7) << 4));
    }

    auto load_stage = [&](int s) {
        uint32_t so = (uint32_t)(s & 1) * F2_STRIDE;
        int k0 = s * F2_KB;
        #pragma unroll
        for (int i = 0; i < 4; i++) cpa16(gDst[i] + so, aSrc[i] + k0);
        #pragma unroll
        for (int i = 0; i < 4; i++) cpa16(gDst[i] + so + F2_STG_A, bSrc[i] + k0);
        cpa_commit();
    };

    const int lane = tid & 31, w = tid >> 5;
    const int wm = w & 3, wn = w >> 2;
    const int matid = lane >> 3, mrow = lane & 7;
    const uint32_t swz = (uint32_t)(mrow << 4);

    uint32_t aRB[2];
    #pragma unroll
    for (int mc = 0; mc < 2; mc++) {
        int row = wm * 32 + mc * 16 + (matid & 1) * 8 + mrow;
        aRB[mc] = sb + row * 128;
    }
    const uint32_t aKS = (uint32_t)((matid >> 1) * 16);

    uint32_t bRB[4];
    #pragma unroll
    for (int nb = 0; nb < 4; nb++) {
        int n = wn * 64 + nb * 16 + (matid >> 1) * 8 + mrow;
        bRB[nb] = sb + F2_STG_A + n * 128;
    }
    const uint32_t bKS = (uint32_t)((matid & 1) * 16);

    float acc[2][8][4] = {};

    load_stage(0);
    load_stage(1);
    for (int s = 0; s < F2_S; s++) {
        if (s == F2_S - 1) cpa_wait<0>(); else cpa_wait<1>();
        __syncthreads();
        const uint32_t so = (uint32_t)(s & 1) * F2_STRIDE;
        #pragma unroll
        for (int ks = 0; ks < 4; ks++) {
            uint32_t aoff = so + ((ks * 32 + aKS) ^ swz);
            uint32_t boff = so + ((ks * 32 + bKS) ^ swz);
            uint32_t aF[2][4], bF[4][4];
            ldsm4(aF[0], aRB[0] + aoff);
            ldsm4(aF[1], aRB[1] + aoff);
            #pragma unroll
            for (int nb = 0; nb < 4; nb++) ldsm4(bF[nb], bRB[nb] + boff);
            #pragma unroll
            for (int mc = 0; mc < 2; mc++)
                #pragma unroll
                for (int nb = 0; nb < 4; nb++) {
                    mma8(acc[mc][nb*2],   aF[mc], &bF[nb][0]);
                    mma8(acc[mc][nb*2+1], aF[mc], &bF[nb][2]);
                }
        }
        __syncthreads();
        if (s + 2 < F2_S) load_stage(s + 2);
    }

    #pragma unroll
    for (int mc = 0; mc < 2; mc++)
        #pragma unroll
        for (int h = 0; h < 2; h++) {
            int r = m0 + wm * 32 + mc * 16 + (lane >> 2) + h * 8;
            if (r < cnt) {
                float* orow = g_o + ((size_t)e * NTOK + r) * DIM + n0 + wn * 64 + (lane & 3) * 2;
                #pragma unroll
                for (int nc = 0; nc < 8; nc++) {
                    float2 v;
                    v.x = acc[mc][nc][h*2+0];
                    v.y = acc[mc][nc][h*2+1];
                    *(float2*)(orow + nc * 8) = v;
                }
            }
        }
}

// ---------------- combine: out[n] = shared[n] + slot1 + slot2 ----------------
__global__ void combine_kernel(float* __restrict__ out) {
    int n = blockIdx.x;
    int2 mp = g_map[n];
    const float* sh = g_o + ((size_t)NE * NTOK + n) * DIM;
    const float* r1 = g_o + (size_t)mp.x * DIM;
    const float* r2 = g_o + (size_t)mp.y * DIM;
    float* o = out + (size_t)n * DIM;
    for (int i = threadIdx.x * 4; i < DIM; i += 1024) {
        float4 a = *(const float4*)(sh + i);
        float4 b = *(const float4*)(r1 + i);
        float4 c = *(const float4*)(r2 + i);
        float4 v;
        v.x = a.x + b.x + c.x; v.y = a.y + b.y + c.y;
        v.z = a.z + b.z + c.z; v.w = a.w + b.w + c.w;
        *(float4*)(o + i) = v;
    }
}

// ---------------- launch ----------------
extern "C" void kernel_launch(void* const* d_in, const int* in_sizes, int n_in,
                              void* d_out, int out_size) {
    const float* x    = (const float*)d_in[0];
    const float* bias = (const float*)d_in[1];
    const float* gw   = (const float*)d_in[2];
    const float* w1   = (const float*)d_in[3];
    const float* w2   = (const float*)d_in[4];
    const float* w3   = (const float*)d_in[5];
    const float* sw1  = (const float*)d_in[6];
    const float* sw2  = (const float*)d_in[7];
    const float* sw3  = (const float*)d_in[8];
    float* out = (float*)d_out;

    cudaFuncSetAttribute(ffn1_mma, cudaFuncAttributeMaxDynamicSharedMemorySize, F1_SMEM);
    cudaFuncSetAttribute(ffn2_mma, cudaFuncAttributeMaxDynamicSharedMemorySize, F2_SMEM);

    // device scratch addresses (host-side symbol lookup is not graph-capturable via
    // cudaMemcpyFromSymbol at capture time? -> use cudaGetSymbolAddress, allowed: no alloc)
    static float *p_xc = nullptr, *p_w1c, *p_w3c, *p_w2c, *p_sw1c, *p_sw2c, *p_sw3c;
    if (!p_xc) {
        cudaGetSymbolAddress((void**)&p_xc,  g_xc);
        cudaGetSymbolAddress((void**)&p_w1c, g_w1c);
        cudaGetSymbolAddress((void**)&p_w3c, g_w3c);
        cudaGetSymbolAddress((void**)&p_w2c, g_w2c);
        cudaGetSymbolAddress((void**)&p_sw1c, g_sw1c);
        cudaGetSymbolAddress((void**)&p_sw2c, g_sw2c);
        cudaGetSymbolAddress((void**)&p_sw3c, g_sw3c);
    }

    reset_kernel<<<1, 32>>>();
    gate_kernel<<<NTOK, 256>>>(x, gw, bias);

    // tf32 pre-round pass
    const int NW = NE * HID * DIM / 4;          // 4.19M float4 per routed weight
    const int NS = HID * DIM / 4;               // shared weight
    const int NX = NTOK * DIM / 4;
    cvt_kernel<<<NX / 256, 256>>>((const float4*)x,   (float4*)p_xc,  NX);
    cvt_kernel<<<NW / 256, 256>>>((const float4*)w1,  (float4*)p_w1c, NW);
    cvt_kernel<<<NW / 256, 256>>>((const float4*)w3,  (float4*)p_w3c, NW);
    cvt_kernel<<<NW / 256, 256>>>((const float4*)w2,  (float4*)p_w2c, NW);
    cvt_kernel<<<NS / 256, 256>>>((const float4*)sw1, (float4*)p_sw1c, NS);
    cvt_kernel<<<NS / 256, 256>>>((const float4*)sw2, (float4*)p_sw2c, NS);
    cvt_kernel<<<NS / 256, 256>>>((const float4*)sw3, (float4*)p_sw3c, NS);

    dim3 g1(NTOK / 128, HID / 64, NE + 1);     // (16, 16, 9)
    ffn1_mma<<<g1, 256, F1_SMEM>>>(p_xc, p_w1c, p_w3c, p_sw1c, p_sw3c);

    dim3 g2(NTOK / 128, DIM / 128, NE + 1);    // (16, 16, 9)
    ffn2_mma<<<g2, 256, F2_SMEM>>>(p_w2c, p_sw2c);

    combine_kernel<<<NTOK, 256>>>(out);
}

// round 8
// speedup vs baseline: 1.6434x; 1.6434x over previous
#include <cuda_runtime.h>
#include <cuda_fp16.h>
#include <cstdint>
#include <math.h>

#define NTOK 2048
#define DIM  2048
#define HID  1024
#define NE   8

// ---------------- device scratch ----------------
__device__ int    g_cnt[NE];
__device__ int    g_tok[NE*NTOK];
__device__ float  g_scr[NE*NTOK];
__device__ int2   g_map[NTOK];
__device__ __half g_h[(size_t)(NE+1)*NTOK*HID];   // per-slot SwiGLU hidden (fp16)
__device__ float  g_o[(size_t)(NE+1)*NTOK*DIM];   // per-slot FFN2 output
// fp16 operand copies
__device__ __half g_xh [(size_t)NTOK*DIM];
__device__ __half g_w1h[(size_t)NE*HID*DIM];
__device__ __half g_w3h[(size_t)NE*HID*DIM];
__device__ __half g_w2h[(size_t)NE*DIM*HID];
__device__ __half g_sw1h[(size_t)HID*DIM];
__device__ __half g_sw2h[(size_t)DIM*HID];
__device__ __half g_sw3h[(size_t)HID*DIM];

// ---------------- PTX helpers ----------------
__device__ __forceinline__ uint32_t smem_u32(const void* p) {
    uint32_t a;
    asm("{ .reg .u64 t; cvta.to.shared.u64 t, %1; cvt.u32.u64 %0, t; }" : "=r"(a) : "l"(p));
    return a;
}
__device__ __forceinline__ void cpa16(uint32_t dst, const void* src) {
    asm volatile("cp.async.cg.shared.global [%0], [%1], 16;"
                 :: "r"(dst), "l"(__cvta_generic_to_global(src)) : "memory");
}
__device__ __forceinline__ void cpa_commit() { asm volatile("cp.async.commit_group;" ::: "memory"); }
template<int N> __device__ __forceinline__ void cpa_wait() {
    asm volatile("cp.async.wait_group %0;" :: "n"(N) : "memory");
}
__device__ __forceinline__ void ldsm4(uint32_t* r, uint32_t addr) {
    asm volatile("ldmatrix.sync.aligned.m8n8.x4.shared.b16 {%0,%1,%2,%3}, [%4];"
                 : "=r"(r[0]), "=r"(r[1]), "=r"(r[2]), "=r"(r[3]) : "r"(addr));
}
// fp16 mma: m16n8k16, fp32 accumulate
__device__ __forceinline__ void mma16(float* d, const uint32_t* a, const uint32_t* b) {
    asm volatile("mma.sync.aligned.m16n8k16.row.col.f32.f16.f16.f32 "
        "{%0,%1,%2,%3}, {%4,%5,%6,%7}, {%8,%9}, {%0,%1,%2,%3};"
        : "+f"(d[0]), "+f"(d[1]), "+f"(d[2]), "+f"(d[3])
        : "r"(a[0]), "r"(a[1]), "r"(a[2]), "r"(a[3]), "r"(b[0]), "r"(b[1]));
}

// ---------------- fp16 convert pass ----------------
__global__ void __launch_bounds__(256)
cvt16_kernel(const float4* __restrict__ src, uint2* __restrict__ dst, int n4) {
    int i = blockIdx.x * blockDim.x + threadIdx.x;
    if (i < n4) {
        float4 v = src[i];
        __half2 h0 = __floats2half2_rn(v.x, v.y);
        __half2 h1 = __floats2half2_rn(v.z, v.w);
        uint2 o;
        o.x = *reinterpret_cast<uint32_t*>(&h0);
        o.y = *reinterpret_cast<uint32_t*>(&h1);
        dst[i] = o;
    }
}

// ---------------- small kernels ----------------
__global__ void reset_kernel() {
    if (threadIdx.x < NE) g_cnt[threadIdx.x] = 0;
}

__global__ void gate_kernel(const float* __restrict__ x,
                            const float* __restrict__ gw,
                            const float* __restrict__ bias) {
    __shared__ float xs[DIM];
    __shared__ float sc[NE];
    int n = blockIdx.x;
    const float* xr = x + (size_t)n * DIM;
    for (int i = threadIdx.x * 4; i < DIM; i += blockDim.x * 4)
        *(float4*)&xs[i] = *(const float4*)&xr[i];
    __syncthreads();

    int w = threadIdx.x >> 5, lane = threadIdx.x & 31;
    if (w < NE) {
        const float* g = gw + (size_t)w * DIM;
        float s = 0.f;
        for (int j = lane * 4; j < DIM; j += 128) {
            float4 xv = *(float4*)&xs[j];
            float4 gv = *(const float4*)&g[j];
            s += xv.x * gv.x + xv.y * gv.y + xv.z * gv.z + xv.w * gv.w;
        }
        #pragma unroll
        for (int o = 16; o > 0; o >>= 1) s += __shfl_xor_sync(0xffffffffu, s, o);
        if (lane == 0) sc[w] = 1.f / (1.f + expf(-s));
    }
    __syncthreads();

    if (threadIdx.x == 0) {
        int b1 = 0; float v1 = sc[0] + bias[0];
        #pragma unroll
        for (int e = 1; e < NE; e++) {
            float v = sc[e] + bias[e];
            if (v > v1) { v1 = v; b1 = e; }
        }
        int b2 = -1; float v2 = -1e30f;
        #pragma unroll
        for (int e = 0; e < NE; e++) {
            if (e == b1) continue;
            float v = sc[e] + bias[e];
            if (v > v2) { v2 = v; b2 = e; }
        }
        int p1 = atomicAdd(&g_cnt[b1], 1);
        g_tok[b1 * NTOK + p1] = n;
        g_scr[b1 * NTOK + p1] = sc[b1];
        int p2 = atomicAdd(&g_cnt[b2], 1);
        g_tok[b2 * NTOK + p2] = n;
        g_scr[b2 * NTOK + p2] = sc[b2];
        g_map[n] = make_int2(b1 * NTOK + p1, b2 * NTOK + p2);
    }
}

// ================= FFN1: dual fp16 mma GEMM + SwiGLU =================
// 256 thr (8 warps, 2 CTAs/SM), tile 128M x 64N dual, warp 32x32 dual.
// K-stage = 64 fp16 (128B row), double-buffered. 32 stages over DIM.
#define F1_KS     64
#define F1_STG_A  16384
#define F1_STG_B  8192
#define F1_STRIDE (F1_STG_A + 2*F1_STG_B)   // 32768
#define F1_SMEM   (2*F1_STRIDE)             // 65536
#define F1_S      (DIM/F1_KS)               // 32

__global__ void __launch_bounds__(256, 2)
ffn1_mma(const __half* __restrict__ xh,
         const __half* __restrict__ w1, const __half* __restrict__ w3,
         const __half* __restrict__ sw1, const __half* __restrict__ sw3)
{
    extern __shared__ char smem[];
    __shared__ int toks[128];
    const int e   = blockIdx.z;
    const int cnt = (e < NE) ? g_cnt[e] : NTOK;
    const int m0  = blockIdx.x * 128;
    if (m0 >= cnt) return;
    const int n0  = blockIdx.y * 64;
    const __half* W1 = (e < NE) ? w1 + (size_t)e * HID * DIM : sw1;
    const __half* W3 = (e < NE) ? w3 + (size_t)e * HID * DIM : sw3;

    const int tid = threadIdx.x;
    if (tid < 128) {
        int r = m0 + tid;
        toks[tid] = (e < NE) ? g_tok[e * NTOK + (r < cnt ? r : cnt - 1)] : r;
    }
    __syncthreads();
    const uint32_t sb = smem_u32(smem);

    // cp.async granules (16B = 8 halves): A 128x8=1024 (4/thr), B1/B3 64x8=512 (2/thr each)
    const __half* aSrc[4]; uint32_t aDst[4];
    #pragma unroll
    for (int i = 0; i < 4; i++) {
        int g = tid + i * 256, row = g >> 3, seg = g & 7;
        aSrc[i] = xh + (size_t)toks[row] * DIM + seg * 8;
        aDst[i] = sb + row * 128 + ((seg * 16) ^ ((row & 7) << 4));
    }
    const __half *b1Src[2], *b3Src[2]; uint32_t bDst[2];
    #pragma unroll
    for (int i = 0; i < 2; i++) {
        int g = tid + i * 256, row = g >> 3, seg = g & 7;   // row 0..63
        b1Src[i] = W1 + (size_t)(n0 + row) * DIM + seg * 8;
        b3Src[i] = W3 + (size_t)(n0 + row) * DIM + seg * 8;
        bDst[i]  = sb + F1_STG_A + row * 128 + ((seg * 16) ^ ((row & 7) << 4));
    }

    auto load_stage = [&](int s) {
        uint32_t so = (uint32_t)(s & 1) * F1_STRIDE;
        int k0 = s * F1_KS;
        #pragma unroll
        for (int i = 0; i < 4; i++) cpa16(aDst[i] + so, aSrc[i] + k0);
        #pragma unroll
        for (int i = 0; i < 2; i++) cpa16(bDst[i] + so, b1Src[i] + k0);
        #pragma unroll
        for (int i = 0; i < 2; i++) cpa16(bDst[i] + so + F1_STG_B, b3Src[i] + k0);
        cpa_commit();
    };

    // warp grid 4(m) x 2(n); warp tile 32m x 32n (dual G/U)
    const int lane = tid & 31, w = tid >> 5;
    const int wm = w & 3, wn = w >> 2;
    const int matid = lane >> 3, mrow = lane & 7;
    const uint32_t swz = (uint32_t)(mrow << 4);

    // A frag groups: g0=(r,k0) g1=(r+8,k0) g2=(r,k+8) g3=(r+8,k+8)
    uint32_t aRB[2];
    #pragma unroll
    for (int mc = 0; mc < 2; mc++) {
        int row = wm * 32 + mc * 16 + (matid & 1) * 8 + mrow;
        aRB[mc] = sb + row * 128;
    }
    const uint32_t aKS = (uint32_t)((matid >> 1) * 16);   // +16B = +8 fp16 k-cols

    // B frag groups: g0=(n,k0) g1=(n,k+8) g2=(n+8,k0) g3=(n+8,k+8)
    uint32_t bRB[2];
    #pragma unroll
    for (int nb = 0; nb < 2; nb++) {
        int n = wn * 32 + nb * 16 + (matid >> 1) * 8 + mrow;
        bRB[nb] = sb + F1_STG_A + n * 128;
    }
    const uint32_t bKS = (uint32_t)((matid & 1) * 16);

    float accG[2][4][4] = {};
    float accU[2][4][4] = {};

    load_stage(0);
    load_stage(1);
    for (int s = 0; s < F1_S; s++) {
        if (s == F1_S - 1) cpa_wait<0>(); else cpa_wait<1>();
        __syncthreads();
        const uint32_t so = (uint32_t)(s & 1) * F1_STRIDE;
        #pragma unroll
        for (int ks = 0; ks < 4; ks++) {          // 4 x k16 = K64
            uint32_t aoff = so + ((ks * 32 + aKS) ^ swz);
            uint32_t boff = so + ((ks * 32 + bKS) ^ swz);
            uint32_t aF[2][4], bF1[2][4], bF3[2][4];
            ldsm4(aF[0], aRB[0] + aoff);
            ldsm4(aF[1], aRB[1] + aoff);
            #pragma unroll
            for (int nb = 0; nb < 2; nb++) {
                ldsm4(bF1[nb], bRB[nb] + boff);
                ldsm4(bF3[nb], bRB[nb] + boff + F1_STG_B);
            }
            #pragma unroll
            for (int mc = 0; mc < 2; mc++)
                #pragma unroll
                for (int nb = 0; nb < 2; nb++) {
                    mma16(accG[mc][nb*2],   aF[mc], &bF1[nb][0]);
                    mma16(accG[mc][nb*2+1], aF[mc], &bF1[nb][2]);
                    mma16(accU[mc][nb*2],   aF[mc], &bF3[nb][0]);
                    mma16(accU[mc][nb*2+1], aF[mc], &bF3[nb][2]);
                }
        }
        __syncthreads();
        if (s + 2 < F1_S) load_stage(s + 2);
    }

    // epilogue: h = fp16( silu(sc*g) * (sc*u) )
    #pragma unroll
    for (int mc = 0; mc < 2; mc++)
        #pragma unroll
        for (int h = 0; h < 2; h++) {
            int r = m0 + wm * 32 + mc * 16 + (lane >> 2) + h * 8;
            if (r < cnt) {
                float scv = (e < NE) ? g_scr[e * NTOK + r] : 1.f;
                __half* hrow = g_h + ((size_t)e * NTOK + r) * HID + n0 + wn * 32 + (lane & 3) * 2;
                #pragma unroll
                for (int nc = 0; nc < 4; nc++) {
                    float g0 = accG[mc][nc][h*2+0] * scv, u0 = accU[mc][nc][h*2+0] * scv;
                    float g1 = accG[mc][nc][h*2+1] * scv, u1 = accU[mc][nc][h*2+1] * scv;
                    float v0 = g0 * (1.f / (1.f + __expf(-g0))) * u0;
                    float v1 = g1 * (1.f / (1.f + __expf(-g1))) * u1;
                    *(__half2*)(hrow + nc * 8) = __floats2half2_rn(v0, v1);
                }
            }
        }
}

// ================= FFN2: fp16 mma GEMM =================
// 256 thr (8 warps, 2 CTAs/SM), tile 128M x 128N, warp 32x64. K-stage 64 fp16.
#define F2_KS     64
#define F2_STG_A  16384
#define F2_STG_B  16384
#define F2_STRIDE (F2_STG_A + F2_STG_B)     // 32768
#define F2_SMEM   (2*F2_STRIDE)             // 65536
#define F2_S      (HID/F2_KS)               // 16

__global__ void __launch_bounds__(256, 2)
ffn2_mma(const __half* __restrict__ w2, const __half* __restrict__ sw2)
{
    extern __shared__ char smem[];
    const int e   = blockIdx.z;
    const int cnt = (e < NE) ? g_cnt[e] : NTOK;
    const int m0  = blockIdx.x * 128;
    if (m0 >= cnt) return;
    const int n0  = blockIdx.y * 128;
    const __half* W2 = (e < NE) ? w2 + (size_t)e * DIM * HID : sw2;
    const __half* A  = g_h + ((size_t)e * NTOK + m0) * HID;

    const int tid = threadIdx.x;
    const uint32_t sb = smem_u32(smem);

    const __half *aSrc[4], *bSrc[4]; uint32_t gDst[4];
    #pragma unroll
    for (int i = 0; i < 4; i++) {
        int g = tid + i * 256, row = g >> 3, seg = g & 7;
        aSrc[i] = A  + (size_t)row * HID + seg * 8;
        bSrc[i] = W2 + (size_t)(n0 + row) * HID + seg * 8;
        gDst[i] = sb + row * 128 + ((seg * 16) ^ ((row & 7) << 4));
    }

    auto load_stage = [&](int s) {
        uint32_t so = (uint32_t)(s & 1) * F2_STRIDE;
        int k0 = s * F2_KS;
        #pragma unroll
        for (int i = 0; i < 4; i++) cpa16(gDst[i] + so, aSrc[i] + k0);
        #pragma unroll
        for (int i = 0; i < 4; i++) cpa16(gDst[i] + so + F2_STG_A, bSrc[i] + k0);
        cpa_commit();
    };

    const int lane = tid & 31, w = tid >> 5;
    const int wm = w & 3, wn = w >> 2;
    const int matid = lane >> 3, mrow = lane & 7;
    const uint32_t swz = (uint32_t)(mrow << 4);

    uint32_t aRB[2];
    #pragma unroll
    for (int mc = 0; mc < 2; mc++) {
        int row = wm * 32 + mc * 16 + (matid & 1) * 8 + mrow;
        aRB[mc] = sb + row * 128;
    }
    const uint32_t aKS = (uint32_t)((matid >> 1) * 16);

    uint32_t bRB[4];
    #pragma unroll
    for (int nb = 0; nb < 4; nb++) {
        int n = wn * 64 + nb * 16 + (matid >> 1) * 8 + mrow;
        bRB[nb] = sb + F2_STG_A + n * 128;
    }
    const uint32_t bKS = (uint32_t)((matid & 1) * 16);

    float acc[2][8][4] = {};

    load_stage(0);
    load_stage(1);
    for (int s = 0; s < F2_S; s++) {
        if (s == F2_S - 1) cpa_wait<0>(); else cpa_wait<1>();
        __syncthreads();
        const uint32_t so = (uint32_t)(s & 1) * F2_STRIDE;
        #pragma unroll
        for (int ks = 0; ks < 4; ks++) {
            uint32_t aoff = so + ((ks * 32 + aKS) ^ swz);
            uint32_t boff = so + ((ks * 32 + bKS) ^ swz);
            uint32_t aF[2][4], bF[4][4];
            ldsm4(aF[0], aRB[0] + aoff);
            ldsm4(aF[1], aRB[1] + aoff);
            #pragma unroll
            for (int nb = 0; nb < 4; nb++) ldsm4(bF[nb], bRB[nb] + boff);
            #pragma unroll
            for (int mc = 0; mc < 2; mc++)
                #pragma unroll
                for (int nb = 0; nb < 4; nb++) {
                    mma16(acc[mc][nb*2],   aF[mc], &bF[nb][0]);
                    mma16(acc[mc][nb*2+1], aF[mc], &bF[nb][2]);
                }
        }
        __syncthreads();
        if (s + 2 < F2_S) load_stage(s + 2);
    }

    #pragma unroll
    for (int mc = 0; mc < 2; mc++)
        #pragma unroll
        for (int h = 0; h < 2; h++) {
            int r = m0 + wm * 32 + mc * 16 + (lane >> 2) + h * 8;
            if (r < cnt) {
                float* orow = g_o + ((size_t)e * NTOK + r) * DIM + n0 + wn * 64 + (lane & 3) * 2;
                #pragma unroll
                for (int nc = 0; nc < 8; nc++) {
                    float2 v;
                    v.x = acc[mc][nc][h*2+0];
                    v.y = acc[mc][nc][h*2+1];
                    *(float2*)(orow + nc * 8) = v;
                }
            }
        }
}

// ---------------- combine: out[n] = shared[n] + slot1 + slot2 ----------------
__global__ void combine_kernel(float* __restrict__ out) {
    int n = blockIdx.x;
    int2 mp = g_map[n];
    const float* sh = g_o + ((size_t)NE * NTOK + n) * DIM;
    const float* r1 = g_o + (size_t)mp.x * DIM;
    const float* r2 = g_o + (size_t)mp.y * DIM;
    float* o = out + (size_t)n * DIM;
    for (int i = threadIdx.x * 4; i < DIM; i += 1024) {
        float4 a = *(const float4*)(sh + i);
        float4 b = *(const float4*)(r1 + i);
        float4 c = *(const float4*)(r2 + i);
        float4 v;
        v.x = a.x + b.x + c.x; v.y = a.y + b.y + c.y;
        v.z = a.z + b.z + c.z; v.w = a.w + b.w + c.w;
        *(float4*)(o + i) = v;
    }
}

// ---------------- launch ----------------
extern "C" void kernel_launch(void* const* d_in, const int* in_sizes, int n_in,
                              void* d_out, int out_size) {
    const float* x    = (const float*)d_in[0];
    const float* bias = (const float*)d_in[1];
    const float* gw   = (const float*)d_in[2];
    const float* w1   = (const float*)d_in[3];
    const float* w2   = (const float*)d_in[4];
    const float* w3   = (const float*)d_in[5];
    const float* sw1  = (const float*)d_in[6];
    const float* sw2  = (const float*)d_in[7];
    const float* sw3  = (const float*)d_in[8];
    float* out = (float*)d_out;

    cudaFuncSetAttribute(ffn1_mma, cudaFuncAttributeMaxDynamicSharedMemorySize, F1_SMEM);
    cudaFuncSetAttribute(ffn2_mma, cudaFuncAttributeMaxDynamicSharedMemorySize, F2_SMEM);

    static __half *p_xh = nullptr, *p_w1h, *p_w3h, *p_w2h, *p_sw1h, *p_sw2h, *p_sw3h;
    if (!p_xh) {
        cudaGetSymbolAddress((void**)&p_xh,  g_xh);
        cudaGetSymbolAddress((void**)&p_w1h, g_w1h);
        cudaGetSymbolAddress((void**)&p_w3h, g_w3h);
        cudaGetSymbolAddress((void**)&p_w2h, g_w2h);
        cudaGetSymbolAddress((void**)&p_sw1h, g_sw1h);
        cudaGetSymbolAddress((void**)&p_sw2h, g_sw2h);
        cudaGetSymbolAddress((void**)&p_sw3h, g_sw3h);
    }

    reset_kernel<<<1, 32>>>();
    gate_kernel<<<NTOK, 256>>>(x, gw, bias);

    // fp16 convert pass
    const int NW = NE * HID * DIM / 4;
    const int NS = HID * DIM / 4;
    const int NX = NTOK * DIM / 4;
    cvt16_kernel<<<NX / 256, 256>>>((const float4*)x,   (uint2*)p_xh,  NX);
    cvt16_kernel<<<NW / 256, 256>>>((const float4*)w1,  (uint2*)p_w1h, NW);
    cvt16_kernel<<<NW / 256, 256>>>((const float4*)w3,  (uint2*)p_w3h, NW);
    cvt16_kernel<<<NW / 256, 256>>>((const float4*)w2,  (uint2*)p_w2h, NW);
    cvt16_kernel<<<NS / 256, 256>>>((const float4*)sw1, (uint2*)p_sw1h, NS);
    cvt16_kernel<<<NS / 256, 256>>>((const float4*)sw2, (uint2*)p_sw2h, NS);
    cvt16_kernel<<<NS / 256, 256>>>((const float4*)sw3, (uint2*)p_sw3h, NS);

    dim3 g1(NTOK / 128, HID / 64, NE + 1);     // (16, 16, 9)
    ffn1_mma<<<g1, 256, F1_SMEM>>>(p_xh, p_w1h, p_w3h, p_sw1h, p_sw3h);

    dim3 g2(NTOK / 128, DIM / 128, NE + 1);    // (16, 16, 9)
    ffn2_mma<<<g2, 256, F2_SMEM>>>(p_w2h, p_sw2h);

    combine_kernel<<<NTOK, 256>>>(out);
}

// round 9
// speedup vs baseline: 1.6534x; 1.0061x over previous
#include <cuda_runtime.h>
#include <cuda_fp16.h>
#include <cstdint>
#include <math.h>

#define NTOK 2048
#define DIM  2048
#define HID  1024
#define NE   8

// ---------------- device scratch ----------------
__device__ int    g_cnt[NE];
__device__ int    g_tok[NE*NTOK];
__device__ float  g_scr[NE*NTOK];
__device__ int2   g_map[NTOK];
__device__ __half g_h[(size_t)(NE+1)*NTOK*HID];   // per-slot SwiGLU hidden (fp16)
__device__ float  g_o[(size_t)(NE+1)*NTOK*DIM];   // per-slot FFN2 output
// fp16 operand copies
__device__ __half g_xh [(size_t)NTOK*DIM];
__device__ __half g_w1h[(size_t)NE*HID*DIM];
__device__ __half g_w3h[(size_t)NE*HID*DIM];
__device__ __half g_w2h[(size_t)NE*DIM*HID];
__device__ __half g_sw1h[(size_t)HID*DIM];
__device__ __half g_sw2h[(size_t)DIM*HID];
__device__ __half g_sw3h[(size_t)HID*DIM];

// ---------------- PTX helpers ----------------
__device__ __forceinline__ uint32_t smem_u32(const void* p) {
    uint32_t a;
    asm("{ .reg .u64 t; cvta.to.shared.u64 t, %1; cvt.u32.u64 %0, t; }" : "=r"(a) : "l"(p));
    return a;
}
__device__ __forceinline__ void cpa16(uint32_t dst, const void* src) {
    asm volatile("cp.async.cg.shared.global [%0], [%1], 16;"
                 :: "r"(dst), "l"(__cvta_generic_to_global(src)) : "memory");
}
__device__ __forceinline__ void cpa_commit() { asm volatile("cp.async.commit_group;" ::: "memory"); }
template<int N> __device__ __forceinline__ void cpa_wait() {
    asm volatile("cp.async.wait_group %0;" :: "n"(N) : "memory");
}
__device__ __forceinline__ void ldsm4(uint32_t* r, uint32_t addr) {
    asm volatile("ldmatrix.sync.aligned.m8n8.x4.shared.b16 {%0,%1,%2,%3}, [%4];"
                 : "=r"(r[0]), "=r"(r[1]), "=r"(r[2]), "=r"(r[3]) : "r"(addr));
}
// fp16 mma: m16n8k16, fp32 accumulate
__device__ __forceinline__ void mma16(float* d, const uint32_t* a, const uint32_t* b) {
    asm volatile("mma.sync.aligned.m16n8k16.row.col.f32.f16.f16.f32 "
        "{%0,%1,%2,%3}, {%4,%5,%6,%7}, {%8,%9}, {%0,%1,%2,%3};"
        : "+f"(d[0]), "+f"(d[1]), "+f"(d[2]), "+f"(d[3])
        : "r"(a[0]), "r"(a[1]), "r"(a[2]), "r"(a[3]), "r"(b[0]), "r"(b[1]));
}

// ---------------- fp16 convert pass ----------------
__global__ void __launch_bounds__(256)
cvt16_kernel(const float4* __restrict__ src, uint2* __restrict__ dst, int n4) {
    int i = blockIdx.x * blockDim.x + threadIdx.x;
    if (i < n4) {
        float4 v = src[i];
        __half2 h0 = __floats2half2_rn(v.x, v.y);
        __half2 h1 = __floats2half2_rn(v.z, v.w);
        uint2 o;
        o.x = *reinterpret_cast<uint32_t*>(&h0);
        o.y = *reinterpret_cast<uint32_t*>(&h1);
        dst[i] = o;
    }
}

// ---------------- small kernels ----------------
__global__ void reset_kernel() {
    if (threadIdx.x < NE) g_cnt[threadIdx.x] = 0;
}

__global__ void gate_kernel(const float* __restrict__ x,
                            const float* __restrict__ gw,
                            const float* __restrict__ bias) {
    __shared__ float xs[DIM];
    __shared__ float sc[NE];
    int n = blockIdx.x;
    const float* xr = x + (size_t)n * DIM;
    for (int i = threadIdx.x * 4; i < DIM; i += blockDim.x * 4)
        *(float4*)&xs[i] = *(const float4*)&xr[i];
    __syncthreads();

    int w = threadIdx.x >> 5, lane = threadIdx.x & 31;
    if (w < NE) {
        const float* g = gw + (size_t)w * DIM;
        float s = 0.f;
        for (int j = lane * 4; j < DIM; j += 128) {
            float4 xv = *(float4*)&xs[j];
            float4 gv = *(const float4*)&g[j];
            s += xv.x * gv.x + xv.y * gv.y + xv.z * gv.z + xv.w * gv.w;
        }
        #pragma unroll
        for (int o = 16; o > 0; o >>= 1) s += __shfl_xor_sync(0xffffffffu, s, o);
        if (lane == 0) sc[w] = 1.f / (1.f + expf(-s));
    }
    __syncthreads();

    if (threadIdx.x == 0) {
        int b1 = 0; float v1 = sc[0] + bias[0];
        #pragma unroll
        for (int e = 1; e < NE; e++) {
            float v = sc[e] + bias[e];
            if (v > v1) { v1 = v; b1 = e; }
        }
        int b2 = -1; float v2 = -1e30f;
        #pragma unroll
        for (int e = 0; e < NE; e++) {
            if (e == b1) continue;
            float v = sc[e] + bias[e];
            if (v > v2) { v2 = v; b2 = e; }
        }
        int p1 = atomicAdd(&g_cnt[b1], 1);
        g_tok[b1 * NTOK + p1] = n;
        g_scr[b1 * NTOK + p1] = sc[b1];
        int p2 = atomicAdd(&g_cnt[b2], 1);
        g_tok[b2 * NTOK + p2] = n;
        g_scr[b2 * NTOK + p2] = sc[b2];
        g_map[n] = make_int2(b1 * NTOK + p1, b2 * NTOK + p2);
    }
}

// ================= FFN1: dual fp16 mma GEMM + SwiGLU =================
// 256 thr (8 warps, 2 CTAs/SM), tile 128M x 64N dual, warp 32x32 dual.
// K-stage = 64 fp16 (128B row), double-buffered. 32 stages over DIM.
#define F1_KS     64
#define F1_STG_A  16384
#define F1_STG_B  8192
#define F1_STRIDE (F1_STG_A + 2*F1_STG_B)   // 32768
#define F1_SMEM   (2*F1_STRIDE)             // 65536
#define F1_S      (DIM/F1_KS)               // 32

__global__ void __launch_bounds__(256, 2)
ffn1_mma(const __half* __restrict__ xh,
         const __half* __restrict__ w1, const __half* __restrict__ w3,
         const __half* __restrict__ sw1, const __half* __restrict__ sw3)
{
    extern __shared__ char smem[];
    __shared__ int toks[128];
    const int e   = blockIdx.z;
    const int cnt = (e < NE) ? g_cnt[e] : NTOK;
    const int m0  = blockIdx.x * 128;
    if (m0 >= cnt) return;
    const int n0  = blockIdx.y * 64;
    const __half* W1 = (e < NE) ? w1 + (size_t)e * HID * DIM : sw1;
    const __half* W3 = (e < NE) ? w3 + (size_t)e * HID * DIM : sw3;

    const int tid = threadIdx.x;
    if (tid < 128) {
        int r = m0 + tid;
        toks[tid] = (e < NE) ? g_tok[e * NTOK + (r < cnt ? r : cnt - 1)] : r;
    }
    __syncthreads();
    const uint32_t sb = smem_u32(smem);

    // cp.async granules (16B = 8 halves): A 128x8=1024 (4/thr), B1/B3 64x8=512 (2/thr each)
    const __half* aSrc[4]; uint32_t aDst[4];
    #pragma unroll
    for (int i = 0; i < 4; i++) {
        int g = tid + i * 256, row = g >> 3, seg = g & 7;
        aSrc[i] = xh + (size_t)toks[row] * DIM + seg * 8;
        aDst[i] = sb + row * 128 + ((seg * 16) ^ ((row & 7) << 4));
    }
    const __half *b1Src[2], *b3Src[2]; uint32_t bDst[2];
    #pragma unroll
    for (int i = 0; i < 2; i++) {
        int g = tid + i * 256, row = g >> 3, seg = g & 7;   // row 0..63
        b1Src[i] = W1 + (size_t)(n0 + row) * DIM + seg * 8;
        b3Src[i] = W3 + (size_t)(n0 + row) * DIM + seg * 8;
        bDst[i]  = sb + F1_STG_A + row * 128 + ((seg * 16) ^ ((row & 7) << 4));
    }

    auto load_stage = [&](int s) {
        uint32_t so = (uint32_t)(s & 1) * F1_STRIDE;
        int k0 = s * F1_KS;
        #pragma unroll
        for (int i = 0; i < 4; i++) cpa16(aDst[i] + so, aSrc[i] + k0);
        #pragma unroll
        for (int i = 0; i < 2; i++) cpa16(bDst[i] + so, b1Src[i] + k0);
        #pragma unroll
        for (int i = 0; i < 2; i++) cpa16(bDst[i] + so + F1_STG_B, b3Src[i] + k0);
        cpa_commit();
    };

    // warp grid 4(m) x 2(n); warp tile 32m x 32n (dual G/U)
    const int lane = tid & 31, w = tid >> 5;
    const int wm = w & 3, wn = w >> 2;
    const int matid = lane >> 3, mrow = lane & 7;
    const uint32_t swz = (uint32_t)(mrow << 4);

    // A frag groups: g0=(r,k0) g1=(r+8,k0) g2=(r,k+8) g3=(r+8,k+8)
    uint32_t aRB[2];
    #pragma unroll
    for (int mc = 0; mc < 2; mc++) {
        int row = wm * 32 + mc * 16 + (matid & 1) * 8 + mrow;
        aRB[mc] = sb + row * 128;
    }
    const uint32_t aKS = (uint32_t)((matid >> 1) * 16);   // +16B = +8 fp16 k-cols

    // B frag groups: g0=(n,k0) g1=(n,k+8) g2=(n+8,k0) g3=(n+8,k+8)
    uint32_t bRB[2];
    #pragma unroll
    for (int nb = 0; nb < 2; nb++) {
        int n = wn * 32 + nb * 16 + (matid >> 1) * 8 + mrow;
        bRB[nb] = sb + F1_STG_A + n * 128;
    }
    const uint32_t bKS = (uint32_t)((matid & 1) * 16);

    float accG[2][4][4] = {};
    float accU[2][4][4] = {};

    load_stage(0);
    load_stage(1);
    for (int s = 0; s < F1_S; s++) {
        if (s == F1_S - 1) cpa_wait<0>(); else cpa_wait<1>();
        __syncthreads();
        const uint32_t so = (uint32_t)(s & 1) * F1_STRIDE;
        #pragma unroll
        for (int ks = 0; ks < 4; ks++) {          // 4 x k16 = K64
            uint32_t aoff = so + ((ks * 32 + aKS) ^ swz);
            uint32_t boff = so + ((ks * 32 + bKS) ^ swz);
            uint32_t aF[2][4], bF1[2][4], bF3[2][4];
            ldsm4(aF[0], aRB[0] + aoff);
            ldsm4(aF[1], aRB[1] + aoff);
            #pragma unroll
            for (int nb = 0; nb < 2; nb++) {
                ldsm4(bF1[nb], bRB[nb] + boff);
                ldsm4(bF3[nb], bRB[nb] + boff + F1_STG_B);
            }
            #pragma unroll
            for (int mc = 0; mc < 2; mc++)
                #pragma unroll
                for (int nb = 0; nb < 2; nb++) {
                    mma16(accG[mc][nb*2],   aF[mc], &bF1[nb][0]);
                    mma16(accG[mc][nb*2+1], aF[mc], &bF1[nb][2]);
                    mma16(accU[mc][nb*2],   aF[mc], &bF3[nb][0]);
                    mma16(accU[mc][nb*2+1], aF[mc], &bF3[nb][2]);
                }
        }
        __syncthreads();
        if (s + 2 < F1_S) load_stage(s + 2);
    }

    // epilogue: h = fp16( silu(sc*g) * (sc*u) )
    #pragma unroll
    for (int mc = 0; mc < 2; mc++)
        #pragma unroll
        for (int h = 0; h < 2; h++) {
            int r = m0 + wm * 32 + mc * 16 + (lane >> 2) + h * 8;
            if (r < cnt) {
                float scv = (e < NE) ? g_scr[e * NTOK + r] : 1.f;
                __half* hrow = g_h + ((size_t)e * NTOK + r) * HID + n0 + wn * 32 + (lane & 3) * 2;
                #pragma unroll
                for (int nc = 0; nc < 4; nc++) {
                    float g0 = accG[mc][nc][h*2+0] * scv, u0 = accU[mc][nc][h*2+0] * scv;
                    float g1 = accG[mc][nc][h*2+1] * scv, u1 = accU[mc][nc][h*2+1] * scv;
                    float v0 = g0 * (1.f / (1.f + __expf(-g0))) * u0;
                    float v1 = g1 * (1.f / (1.f + __expf(-g1))) * u1;
                    *(__half2*)(hrow + nc * 8) = __floats2half2_rn(v0, v1);
                }
            }
        }
}

// ================= FFN2: fp16 mma GEMM =================
// 256 thr (8 warps, 2 CTAs/SM), tile 128M x 128N, warp 32x64. K-stage 64 fp16.
#define F2_KS     64
#define F2_STG_A  16384
#define F2_STG_B  16384
#define F2_STRIDE (F2_STG_A + F2_STG_B)     // 32768
#define F2_SMEM   (2*F2_STRIDE)             // 65536
#define F2_S      (HID/F2_KS)               // 16

__global__ void __launch_bounds__(256, 2)
ffn2_mma(const __half* __restrict__ w2, const __half* __restrict__ sw2)
{
    extern __shared__ char smem[];
    const int e   = blockIdx.z;
    const int cnt = (e < NE) ? g_cnt[e] : NTOK;
    const int m0  = blockIdx.x * 128;
    if (m0 >= cnt) return;
    const int n0  = blockIdx.y * 128;
    const __half* W2 = (e < NE) ? w2 + (size_t)e * DIM * HID : sw2;
    const __half* A  = g_h + ((size_t)e * NTOK + m0) * HID;

    const int tid = threadIdx.x;
    const uint32_t sb = smem_u32(smem);

    const __half *aSrc[4], *bSrc[4]; uint32_t gDst[4];
    #pragma unroll
    for (int i = 0; i < 4; i++) {
        int g = tid + i * 256, row = g >> 3, seg = g & 7;
        aSrc[i] = A  + (size_t)row * HID + seg * 8;
        bSrc[i] = W2 + (size_t)(n0 + row) * HID + seg * 8;
        gDst[i] = sb + row * 128 + ((seg * 16) ^ ((row & 7) << 4));
    }

    auto load_stage = [&](int s) {
        uint32_t so = (uint32_t)(s & 1) * F2_STRIDE;
        int k0 = s * F2_KS;
        #pragma unroll
        for (int i = 0; i < 4; i++) cpa16(gDst[i] + so, aSrc[i] + k0);
        #pragma unroll
        for (int i = 0; i < 4; i++) cpa16(gDst[i] + so + F2_STG_A, bSrc[i] + k0);
        cpa_commit();
    };

    const int lane = tid & 31, w = tid >> 5;
    const int wm = w & 3, wn = w >> 2;
    const int matid = lane >> 3, mrow = lane & 7;
    const uint32_t swz = (uint32_t)(mrow << 4);

    uint32_t aRB[2];
    #pragma unroll
    for (int mc = 0; mc < 2; mc++) {
        int row = wm * 32 + mc * 16 + (matid & 1) * 8 + mrow;
        aRB[mc] = sb + row * 128;
    }
    const uint32_t aKS = (uint32_t)((matid >> 1) * 16);

    uint32_t bRB[4];
    #pragma unroll
    for (int nb = 0; nb < 4; nb++) {
        int n = wn * 64 + nb * 16 + (matid >> 1) * 8 + mrow;
        bRB[nb] = sb + F2_STG_A + n * 128;
    }
    const uint32_t bKS = (uint32_t)((matid & 1) * 16);

    float acc[2][8][4] = {};

    load_stage(0);
    load_stage(1);
    for (int s = 0; s < F2_S; s++) {
        if (s == F2_S - 1) cpa_wait<0>(); else cpa_wait<1>();
        __syncthreads();
        const uint32_t so = (uint32_t)(s & 1) * F2_STRIDE;
        #pragma unroll
        for (int ks = 0; ks < 4; ks++) {
            uint32_t aoff = so + ((ks * 32 + aKS) ^ swz);
            uint32_t boff = so + ((ks * 32 + bKS) ^ swz);
            uint32_t aF[2][4], bF[4][4];
            ldsm4(aF[0], aRB[0] + aoff);
            ldsm4(aF[1], aRB[1] + aoff);
            #pragma unroll
            for (int nb = 0; nb < 4; nb++) ldsm4(bF[nb], bRB[nb] + boff);
            #pragma unroll
            for (int mc = 0; mc < 2; mc++)
                #pragma unroll
                for (int nb = 0; nb < 4; nb++) {
                    mma16(acc[mc][nb*2],   aF[mc], &bF[nb][0]);
                    mma16(acc[mc][nb*2+1], aF[mc], &bF[nb][2]);
                }
        }
        __syncthreads();
        if (s + 2 < F2_S) load_stage(s + 2);
    }

    #pragma unroll
    for (int mc = 0; mc < 2; mc++)
        #pragma unroll
        for (int h = 0; h < 2; h++) {
            int r = m0 + wm * 32 + mc * 16 + (lane >> 2) + h * 8;
            if (r < cnt) {
                float* orow = g_o + ((size_t)e * NTOK + r) * DIM + n0 + wn * 64 + (lane & 3) * 2;
                #pragma unroll
                for (int nc = 0; nc < 8; nc++) {
                    float2 v;
                    v.x = acc[mc][nc][h*2+0];
                    v.y = acc[mc][nc][h*2+1];
                    *(float2*)(orow + nc * 8) = v;
                }
            }
        }
}

// ---------------- combine: out[n] = shared[n] + slot1 + slot2 ----------------
__global__ void combine_kernel(float* __restrict__ out) {
    int n = blockIdx.x;
    int2 mp = g_map[n];
    const float* sh = g_o + ((size_t)NE * NTOK + n) * DIM;
    const float* r1 = g_o + (size_t)mp.x * DIM;
    const float* r2 = g_o + (size_t)mp.y * DIM;
    float* o = out + (size_t)n * DIM;
    for (int i = threadIdx.x * 4; i < DIM; i += 1024) {
        float4 a = *(const float4*)(sh + i);
        float4 b = *(const float4*)(r1 + i);
        float4 c = *(const float4*)(r2 + i);
        float4 v;
        v.x = a.x + b.x + c.x; v.y = a.y + b.y + c.y;
        v.z = a.z + b.z + c.z; v.w = a.w + b.w + c.w;
        *(float4*)(o + i) = v;
    }
}

// ---------------- launch ----------------
extern "C" void kernel_launch(void* const* d_in, const int* in_sizes, int n_in,
                              void* d_out, int out_size) {
    const float* x    = (const float*)d_in[0];
    const float* bias = (const float*)d_in[1];
    const float* gw   = (const float*)d_in[2];
    const float* w1   = (const float*)d_in[3];
    const float* w2   = (const float*)d_in[4];
    const float* w3   = (const float*)d_in[5];
    const float* sw1  = (const float*)d_in[6];
    const float* sw2  = (const float*)d_in[7];
    const float* sw3  = (const float*)d_in[8];
    float* out = (float*)d_out;

    cudaFuncSetAttribute(ffn1_mma, cudaFuncAttributeMaxDynamicSharedMemorySize, F1_SMEM);
    cudaFuncSetAttribute(ffn2_mma, cudaFuncAttributeMaxDynamicSharedMemorySize, F2_SMEM);

    static __half *p_xh = nullptr, *p_w1h, *p_w3h, *p_w2h, *p_sw1h, *p_sw2h, *p_sw3h;
    if (!p_xh) {
        cudaGetSymbolAddress((void**)&p_xh,  g_xh);
        cudaGetSymbolAddress((void**)&p_w1h, g_w1h);
        cudaGetSymbolAddress((void**)&p_w3h, g_w3h);
        cudaGetSymbolAddress((void**)&p_w2h, g_w2h);
        cudaGetSymbolAddress((void**)&p_sw1h, g_sw1h);
        cudaGetSymbolAddress((void**)&p_sw2h, g_sw2h);
        cudaGetSymbolAddress((void**)&p_sw3h, g_sw3h);
    }

    reset_kernel<<<1, 32>>>();
    gate_kernel<<<NTOK, 256>>>(x, gw, bias);

    // fp16 convert pass
    const int NW = NE * HID * DIM / 4;
    const int NS = HID * DIM / 4;
    const int NX = NTOK * DIM / 4;
    cvt16_kernel<<<NX / 256, 256>>>((const float4*)x,   (uint2*)p_xh,  NX);
    cvt16_kernel<<<NW / 256, 256>>>((const float4*)w1,  (uint2*)p_w1h, NW);
    cvt16_kernel<<<NW / 256, 256>>>((const float4*)w3,  (uint2*)p_w3h, NW);
    cvt16_kernel<<<NW / 256, 256>>>((const float4*)w2,  (uint2*)p_w2h, NW);
    cvt16_kernel<<<NS / 256, 256>>>((const float4*)sw1, (uint2*)p_sw1h, NS);
    cvt16_kernel<<<NS / 256, 256>>>((const float4*)sw2, (uint2*)p_sw2h, NS);
    cvt16_kernel<<<NS / 256, 256>>>((const float4*)sw3, (uint2*)p_sw3h, NS);

    dim3 g1(NTOK / 128, HID / 64, NE + 1);     // (16, 16, 9)
    ffn1_mma<<<g1, 256, F1_SMEM>>>(p_xh, p_w1h, p_w3h, p_sw1h, p_sw3h);

    dim3 g2(NTOK / 128, DIM / 128, NE + 1);    // (16, 16, 9)
    ffn2_mma<<<g2, 256, F2_SMEM>>>(p_w2h, p_sw2h);

    combine_kernel<<<NTOK, 256>>>(out);
}